// round 1
// baseline (speedup 1.0000x reference)
#include <cuda_runtime.h>

#define Bb   8
#define Nn   2048
#define Dd   128
#define Fin  10
#define ALPHA 0.02f
#define TI   32
#define CJ   128
#define NCHUNK (Nn / CJ)

// ---------------- device scratch (static allocation is allowed) ----------------
__device__ float g_Wh[Bb * Nn * Dd];      // 8 MB
__device__ float g_e1[Bb * Nn];
__device__ float g_e2[Bb * Nn];
__device__ float g_e2max[Bb];
__device__ float g_pooled[Bb * Dd];

// ---------------- helpers ----------------
__device__ __forceinline__ float warpSum(float v) {
#pragma unroll
    for (int o = 16; o > 0; o >>= 1) v += __shfl_xor_sync(0xffffffffu, v, o);
    return v;
}
__device__ __forceinline__ float warpMax(float v) {
#pragma unroll
    for (int o = 16; o > 0; o >>= 1) v = fmaxf(v, __shfl_xor_sync(0xffffffffu, v, o));
    return v;
}
__device__ __forceinline__ float lrelu(float x) { return x >= 0.f ? x : ALPHA * x; }

__device__ __forceinline__ void atomicMaxFloat(float* addr, float v) {
    if (v >= 0.f) atomicMax((int*)addr, __float_as_int(v));
    else          atomicMin((unsigned int*)addr, __float_as_uint(v));
}

// ---------------- K0: init pooled ----------------
__global__ void k_init() {
    g_pooled[threadIdx.x] = -3.402823466e38f;
}

// ---------------- K1: fc1 + LN + lrelu + Wg GEMM + e1/e2 ----------------
// one block (128 threads) per node
__global__ __launch_bounds__(128) void k1_node(
    const float* __restrict__ h, const float* __restrict__ W1, const float* __restrict__ b1,
    const float* __restrict__ Wg, const float* __restrict__ bg,
    const float* __restrict__ a1, const float* __restrict__ a2)
{
    __shared__ float hsh[Fin];
    __shared__ float xsh[Dd];
    __shared__ float rs1[4], rs2[4];

    const int node = blockIdx.x;       // b*N + i
    const int t = threadIdx.x;
    const int lane = t & 31, wrp = t >> 5;

    if (t < Fin) hsh[t] = h[node * Fin + t];
    __syncthreads();

    float x = b1[t];
#pragma unroll
    for (int f = 0; f < Fin; ++f) x += hsh[f] * W1[t * Fin + f];

    // layernorm over 128
    float s1 = warpSum(x);
    float s2 = warpSum(x * x);
    if (lane == 0) { rs1[wrp] = s1; rs2[wrp] = s2; }
    __syncthreads();
    float S1 = rs1[0] + rs1[1] + rs1[2] + rs1[3];
    float S2 = rs2[0] + rs2[1] + rs2[2] + rs2[3];
    __syncthreads();
    float mean = S1 * (1.f / Dd);
    float var  = S2 * (1.f / Dd) - mean * mean;
    float xn = (x - mean) * rsqrtf(var + 1e-5f);
    xn = lrelu(xn);
    xsh[t] = xn;
    __syncthreads();

    // Wh = x @ Wg^T + bg   (Wg row t cached by L1: 64 KB total)
    float wv = bg[t];
    const float* wgr = Wg + t * Dd;
#pragma unroll 8
    for (int k = 0; k < Dd; ++k) wv += xsh[k] * wgr[k];
    g_Wh[(size_t)node * Dd + t] = wv;

    float p1 = warpSum(wv * a1[t]);
    float p2 = warpSum(wv * a2[t]);
    if (lane == 0) { rs1[wrp] = p1; rs2[wrp] = p2; }
    __syncthreads();
    if (t == 0) {
        g_e1[node] = rs1[0] + rs1[1] + rs1[2] + rs1[3];
        g_e2[node] = rs2[0] + rs2[1] + rs2[2] + rs2[3];
    }
}

// ---------------- K1b: per-batch max of e2 ----------------
__global__ void k_e2max() {
    const int b = blockIdx.x, t = threadIdx.x;
    const int lane = t & 31, wrp = t >> 5;
    __shared__ float sm[4];
    float mx = -3.402823466e38f;
    for (int k = t; k < Nn; k += 128) mx = fmaxf(mx, g_e2[b * Nn + k]);
    mx = warpMax(mx);
    if (lane == 0) sm[wrp] = mx;
    __syncthreads();
    if (t == 0) g_e2max[b] = fmaxf(fmaxf(sm[0], sm[1]), fmaxf(sm[2], sm[3]));
}

// ---------------- K2: masked attention + weighted sum + LN + maxpool ----------------
// grid = B * (N/TI) = 512 blocks, 128 threads.
// Softmax uses the analytic bound m_i = lrelu(e1_i + max_j e2_j) >= all scores,
// so a single streaming pass suffices (no online rescaling).
__global__ __launch_bounds__(128, 2) void k2_attn(const int* __restrict__ adj)
{
    extern __shared__ char smem_raw[];
    float*  wh_sh = (float*)smem_raw;                         // CJ x Dd fp32     (64 KB)
    float2* w_sh  = (float2*)(smem_raw + CJ * Dd * 4);        // TI x CJ float2   (32 KB)

    __shared__ float e1_sh[TI], m_sh[TI], l_sh[TI];
    __shared__ float lred[TI][4];
    __shared__ float rs1[4], rs2[4];

    const int bid = blockIdx.x;
    const int b   = bid / (Nn / TI);
    const int i0  = (bid % (Nn / TI)) * TI;
    const int t   = threadIdx.x;
    const int lane = t & 31, wrp = t >> 5;
    const int u    = t & 63;          // dim-pair index (dims 2u, 2u+1)
    const int jg0  = (t >> 6) * 64;   // j-half handled by this thread in FMA phase

    if (t < TI) {
        float e1v = g_e1[(b << 11) + i0 + t];
        e1_sh[t] = e1v;
        m_sh[t] = lrelu(e1v + g_e2max[b]);
    }

    unsigned long long acc[TI];
#pragma unroll
    for (int i = 0; i < TI; ++i) acc[i] = 0ull;   // packed (0.f, 0.f)
    float lpart[TI];
#pragma unroll
    for (int i = 0; i < TI; ++i) lpart[i] = 0.f;

    __syncthreads();

    for (int c = 0; c < NCHUNK; ++c) {
        const int jbase = c * CJ;

        // stage Wh chunk [CJ x Dd] into smem (coalesced float4)
        {
            const float4* src = (const float4*)(g_Wh + ((size_t)((b << 11) + jbase) << 7));
            float4* dst = (float4*)wh_sh;
#pragma unroll
            for (int it = 0; it < 32; ++it) dst[it * 128 + t] = src[it * 128 + t];
        }

        // scores: thread t <-> column j = jbase + t
        {
            const float e2v = g_e2[(b << 11) + jbase + t];
            const int* adjp = adj + ((long long)(b << 11) + i0) * Nn + jbase + t;
#pragma unroll
            for (int ib = 0; ib < TI; ib += 16) {
                int av[16];
#pragma unroll
                for (int k = 0; k < 16; ++k) av[k] = adjp[(long long)(ib + k) * Nn];
#pragma unroll
                for (int k = 0; k < 16; ++k) {
                    const int i = ib + k;
                    float s = lrelu(e1_sh[i] + e2v);
                    float w = 0.f;
                    if (av[k] != 0) w = __expf(s - m_sh[i]);
                    lpart[i] += w;
                    w_sh[i * CJ + t] = make_float2(w, w);
                }
            }
        }
        __syncthreads();

        // FMA phase: acc[i] += w[i][jg] * Wh[jg][2u:2u+2]   (packed f32x2)
        {
            const unsigned long long* whp = ((const unsigned long long*)wh_sh) + u;
            const unsigned long long* wsp = (const unsigned long long*)w_sh;
#pragma unroll 2
            for (int jj = 0; jj < 64; ++jj) {
                const int jg = jg0 + jj;
                const unsigned long long wh2 = whp[jg * 64];
#pragma unroll
                for (int i = 0; i < TI; ++i) {
                    const unsigned long long w2 = wsp[i * CJ + jg];
                    asm("fma.rn.f32x2 %0, %1, %2, %0;" : "+l"(acc[i]) : "l"(w2), "l"(wh2));
                }
            }
        }
        __syncthreads();
    }

    // reduce l over 128 threads per row
#pragma unroll
    for (int i = 0; i < TI; ++i) {
        float v = warpSum(lpart[i]);
        if (lane == 0) lred[i][wrp] = v;
    }
    __syncthreads();
    if (t < TI) l_sh[t] = lred[t][0] + lred[t][1] + lred[t][2] + lred[t][3];
    __syncthreads();

    // merge the two j-halves; hp = acc / l  -> store rows into wh_sh (reused)
    if (t >= 64) {
#pragma unroll
        for (int i = 0; i < TI; ++i) ((unsigned long long*)w_sh)[i * 64 + u] = acc[i];
    }
    __syncthreads();
    if (t < 64) {
#pragma unroll
        for (int i = 0; i < TI; ++i) {
            float2 a = *(float2*)&acc[i];
            float2 o = *((float2*)w_sh + i * 64 + u);
            float inv = 1.f / l_sh[i];
            wh_sh[i * Dd + 2 * u]     = (a.x + o.x) * inv;
            wh_sh[i * Dd + 2 * u + 1] = (a.y + o.y) * inv;
        }
    }
    __syncthreads();

    // per-row LN + lrelu + global max pool
    for (int i = 0; i < TI; ++i) {
        float v = wh_sh[i * Dd + t];
        float s1 = warpSum(v);
        float s2 = warpSum(v * v);
        if (lane == 0) { rs1[wrp] = s1; rs2[wrp] = s2; }
        __syncthreads();
        float S1 = rs1[0] + rs1[1] + rs1[2] + rs1[3];
        float S2 = rs2[0] + rs2[1] + rs2[2] + rs2[3];
        __syncthreads();
        float mean = S1 * (1.f / Dd);
        float var  = S2 * (1.f / Dd) - mean * mean;
        float nv = (v - mean) * rsqrtf(var + 1e-5f);
        nv = lrelu(nv);
        atomicMaxFloat(&g_pooled[(b << 7) + t], nv);
    }
}

// ---------------- K3: head + log_softmax ----------------
__global__ void k3_out(const float* __restrict__ W2, const float* __restrict__ b2,
                       float* __restrict__ out)
{
    const int t = threadIdx.x;          // 256
    const int b = t >> 5, lane = t & 31;
    if (b < Bb) {
        float p0 = 0.f, p1 = 0.f;
        for (int d = lane; d < Dd; d += 32) {
            float pv = g_pooled[b * Dd + d];
            p0 += pv * W2[d];
            p1 += pv * W2[Dd + d];
        }
        p0 = warpSum(p0);
        p1 = warpSum(p1);
        if (lane == 0) {
            float o0 = p0 + b2[0], o1 = p1 + b2[1];
            float m = fmaxf(o0, o1);
            float lse = m + logf(expf(o0 - m) + expf(o1 - m));
            out[b * 2 + 0] = o0 - lse;
            out[b * 2 + 1] = o1 - lse;
        }
    }
}

// ---------------- launch ----------------
extern "C" void kernel_launch(void* const* d_in, const int* in_sizes, int n_in,
                              void* d_out, int out_size)
{
    const float* h   = (const float*)d_in[0];
    const int*   adj = (const int*)  d_in[1];
    const float* W1  = (const float*)d_in[2];
    const float* b1  = (const float*)d_in[3];
    const float* Wg  = (const float*)d_in[4];
    const float* bg  = (const float*)d_in[5];
    const float* a1  = (const float*)d_in[6];
    const float* a2  = (const float*)d_in[7];
    const float* W2  = (const float*)d_in[8];
    const float* b2  = (const float*)d_in[9];
    float* out = (float*)d_out;

    const int dyn_smem = CJ * Dd * 4 + TI * CJ * 8;   // 98304 bytes
    cudaFuncSetAttribute(k2_attn, cudaFuncAttributeMaxDynamicSharedMemorySize, dyn_smem);

    k_init<<<1, Bb * Dd>>>();
    k1_node<<<Bb * Nn, 128>>>(h, W1, b1, Wg, bg, a1, a2);
    k_e2max<<<Bb, 128>>>();
    k2_attn<<<Bb * (Nn / TI), 128, dyn_smem>>>(adj);
    k3_out<<<1, 256>>>(W2, b2, out);
}

// round 3
// speedup vs baseline: 2.7067x; 2.7067x over previous
#include <cuda_runtime.h>

#define Bb   8
#define Nn   2048
#define Dd   128
#define Fin  10
#define ALPHA 0.02f
#define TI   32
#define CJ   128
#define NCHUNK (Nn / CJ)

typedef unsigned long long ull;

// ---------------- device scratch ----------------
__device__ float g_X [Bb * Nn * Dd];      // 8 MB (post fc1+LN+lrelu)
__device__ float g_Wh[Bb * Nn * Dd];      // 8 MB
__device__ float g_e1[Bb * Nn];
__device__ float g_e2[Bb * Nn];
__device__ float g_e2max[Bb];
__device__ float g_pooled[Bb * Dd];

// ---------------- helpers ----------------
__device__ __forceinline__ float warpSum(float v) {
#pragma unroll
    for (int o = 16; o > 0; o >>= 1) v += __shfl_xor_sync(0xffffffffu, v, o);
    return v;
}
__device__ __forceinline__ float warpMax(float v) {
#pragma unroll
    for (int o = 16; o > 0; o >>= 1) v = fmaxf(v, __shfl_xor_sync(0xffffffffu, v, o));
    return v;
}
__device__ __forceinline__ float lrelu(float x) { return x >= 0.f ? x : ALPHA * x; }

__device__ __forceinline__ void atomicMaxFloat(float* addr, float v) {
    if (v >= 0.f) atomicMax((int*)addr, __float_as_int(v));
    else          atomicMin((unsigned int*)addr, __float_as_uint(v));
}
__device__ __forceinline__ void ffma2(ull& a, ull b, ull c) {
    asm("fma.rn.f32x2 %0, %1, %2, %0;" : "+l"(a) : "l"(b), "l"(c));
}
__device__ __forceinline__ ull packf2(float v) {
    ull r; asm("mov.b64 %0, {%1, %1};" : "=l"(r) : "f"(v)); return r;
}

// ---------------- K0: init pooled ----------------
__global__ void k_init() {
    g_pooled[threadIdx.x] = -3.402823466e38f;
}

// ---------------- K1a: fc1 + LN + lrelu -> g_X ----------------
// one block (128 threads) per node; W1 staged in smem (coalesced)
__global__ __launch_bounds__(128) void k1a(
    const float* __restrict__ h, const float* __restrict__ W1, const float* __restrict__ b1)
{
    __shared__ float w1s[Dd * Fin];
    __shared__ float hsh[Fin];
    __shared__ float rs1[4], rs2[4];

    const int node = blockIdx.x;
    const int t = threadIdx.x;
    const int lane = t & 31, wrp = t >> 5;

#pragma unroll
    for (int idx = t; idx < Dd * Fin; idx += 128) w1s[idx] = W1[idx];
    if (t < Fin) hsh[t] = h[node * Fin + t];
    __syncthreads();

    float x = b1[t];
#pragma unroll
    for (int f = 0; f < Fin; ++f) x += hsh[f] * w1s[t * Fin + f];

    float s1 = warpSum(x);
    float s2 = warpSum(x * x);
    if (lane == 0) { rs1[wrp] = s1; rs2[wrp] = s2; }
    __syncthreads();
    float S1 = rs1[0] + rs1[1] + rs1[2] + rs1[3];
    float S2 = rs2[0] + rs2[1] + rs2[2] + rs2[3];
    float mean = S1 * (1.f / Dd);
    float var  = S2 * (1.f / Dd) - mean * mean;
    float xn = (x - mean) * rsqrtf(var + 1e-5f);
    g_X[(size_t)node * Dd + t] = lrelu(xn);
}

// ---------------- K1b: Wh = X @ Wg^T + bg, plus e1/e2 ----------------
// 128 blocks x 512 threads; per block: 128 nodes. Wg transposed in smem (pad 132).
__global__ __launch_bounds__(512) void k1b(
    const float* __restrict__ Wg, const float* __restrict__ bg,
    const float* __restrict__ a1, const float* __restrict__ a2)
{
    extern __shared__ float sm[];
    float* wgt = sm;                 // [128 k][132] (value at wgt[k*132+d] = Wg[d][k])
    float* xsh = sm + 128 * 132;     // [128 n][128 k]

    const int t = threadIdx.x;
    const int lane = t & 31, wrp = t >> 5;    // wrp 0..15
    const int n0 = blockIdx.x * 128;

    // load Wg transposed
#pragma unroll
    for (int it = 0; it < 32; ++it) {
        int idx = it * 512 + t;
        int d = idx >> 7, k = idx & 127;
        wgt[k * 132 + d] = Wg[idx];
    }
    // load X tile
    {
        const float4* xs = (const float4*)(g_X) + (size_t)n0 * 32;
        float4* xd = (float4*)xsh;
#pragma unroll
        for (int it = 0; it < 8; ++it) xd[it * 512 + t] = xs[it * 512 + t];
    }
    __syncthreads();

    // GEMM: warp wrp -> nodes n0 + wrp*8 .. +8; lane -> dims 4*lane..4*lane+3
    ull acc[8][2];
#pragma unroll
    for (int n = 0; n < 8; ++n) { acc[n][0] = 0ull; acc[n][1] = 0ull; }

    for (int k = 0; k < 128; ++k) {
        ulonglong2 wv = *(const ulonglong2*)&wgt[k * 132 + lane * 4];
#pragma unroll
        for (int n = 0; n < 8; ++n) {
            float xv = xsh[(wrp * 8 + n) * 128 + k];
            ull xx = packf2(xv);
            ffma2(acc[n][0], xx, wv.x);
            ffma2(acc[n][1], xx, wv.y);
        }
    }

    const float4 bgv = ((const float4*)bg)[lane];
    const float4 a1v = ((const float4*)a1)[lane];
    const float4 a2v = ((const float4*)a2)[lane];

#pragma unroll
    for (int n = 0; n < 8; ++n) {
        const int node = n0 + wrp * 8 + n;
        float2 lo = *(float2*)&acc[n][0];
        float2 hi = *(float2*)&acc[n][1];
        float4 wh;
        wh.x = lo.x + bgv.x; wh.y = lo.y + bgv.y;
        wh.z = hi.x + bgv.z; wh.w = hi.y + bgv.w;
        ((float4*)g_Wh)[(size_t)node * 32 + lane] = wh;
        float p1 = wh.x * a1v.x + wh.y * a1v.y + wh.z * a1v.z + wh.w * a1v.w;
        float p2 = wh.x * a2v.x + wh.y * a2v.y + wh.z * a2v.z + wh.w * a2v.w;
        p1 = warpSum(p1);
        p2 = warpSum(p2);
        if (lane == 0) { g_e1[node] = p1; g_e2[node] = p2; }
    }
}

// ---------------- K1c: per-batch max of e2 ----------------
__global__ void k_e2max() {
    const int b = blockIdx.x, t = threadIdx.x;
    const int lane = t & 31, wrp = t >> 5;
    __shared__ float sm[4];
    float mx = -3.402823466e38f;
    for (int k = t; k < Nn; k += 128) mx = fmaxf(mx, g_e2[b * Nn + k]);
    mx = warpMax(mx);
    if (lane == 0) sm[wrp] = mx;
    __syncthreads();
    if (t == 0) g_e2max[b] = fmaxf(fmaxf(sm[0], sm[1]), fmaxf(sm[2], sm[3]));
}

// ---------------- K2: masked attention + weighted sum + LN + maxpool ----------------
// grid = B*(N/TI) = 512 blocks, 128 threads. Lane owns 4 dims (float4 acc as 2xf32x2),
// warps split j into quarters per chunk. w stored scalar in smem, read LDS.32 broadcast.
// Softmax max uses analytic bound m_i = lrelu(e1_i + max_j e2_j) -> one streaming pass.
__global__ __launch_bounds__(128, 2) void k2_attn(const int* __restrict__ adj)
{
    extern __shared__ char smraw[];
    float* wh_sh = (float*)smraw;                    // [CJ j][Dd d]   64 KB
    float* w_sh  = (float*)(smraw + CJ * Dd * 4);    // [TI i][CJ j]   16 KB

    __shared__ float e1_sh[TI], m_sh[TI], l_sh[TI];
    __shared__ float lsum[TI][4];
    __shared__ float rs1[4], rs2[4];

    const int bid = blockIdx.x;
    const int b   = bid >> 6;              // 64 blocks per batch
    const int i0  = (bid & 63) * TI;
    const int t   = threadIdx.x;
    const int lane = t & 31, wrp = t >> 5;

    if (t < TI) {
        float e1v = g_e1[(b << 11) + i0 + t];
        e1_sh[t] = e1v;
        m_sh[t]  = lrelu(e1v + g_e2max[b]);
        lsum[t][0] = lsum[t][1] = lsum[t][2] = lsum[t][3] = 0.f;
    }

    ull acc[2 * TI];
#pragma unroll
    for (int i = 0; i < 2 * TI; ++i) acc[i] = 0ull;

    __syncthreads();

    for (int c = 0; c < NCHUNK; ++c) {
        const int jb = c * CJ;

        // stage Wh chunk [CJ x Dd]
        {
            const float4* src = (const float4*)(g_Wh + ((size_t)((b << 11) + jb) << 7));
            float4* dst = (float4*)wh_sh;
#pragma unroll
            for (int it = 0; it < 32; ++it) dst[it * 128 + t] = src[it * 128 + t];
        }

        // scores: thread t <-> column j = jb + t ; scalar w to smem; l reduced now
        {
            const float e2v = g_e2[(b << 11) + jb + t];
            const int* adjp = adj + ((size_t)((b << 11) + i0)) * Nn + jb + t;
#pragma unroll
            for (int hb = 0; hb < TI; hb += 16) {
                int av[16];
#pragma unroll
                for (int k = 0; k < 16; ++k) av[k] = adjp[(size_t)(hb + k) * Nn];
                float w[16];
#pragma unroll
                for (int k = 0; k < 16; ++k) {
                    const int i = hb + k;
                    float s = lrelu(e1_sh[i] + e2v);
                    w[k] = (av[k] != 0) ? __expf(s - m_sh[i]) : 0.f;
                    w_sh[i * CJ + t] = w[k];
                }
#pragma unroll
                for (int k = 0; k < 16; ++k) {
                    float v = warpSum(w[k]);
                    if (lane == 0) lsum[hb + k][wrp] += v;
                }
            }
        }
        __syncthreads();

        // FMA: warp handles j-quarter [wrp*32, wrp*32+32)
        {
            const ulonglong2* whq = (const ulonglong2*)wh_sh;   // [j][32 lane-chunks]
            const float* wrow = w_sh + (wrp << 5);
            ulonglong2 whn = whq[(wrp << 5) * 32 + lane];
#pragma unroll 1
            for (int jj = 0; jj < 32; ++jj) {
                ulonglong2 wh2 = whn;
                int jn = (wrp << 5) + ((jj + 1) & 31);
                whn = whq[jn * 32 + lane];
#pragma unroll
                for (int i = 0; i < TI; ++i) {
                    ull ww = packf2(wrow[i * CJ + jj]);
                    ffma2(acc[2 * i],     ww, wh2.x);
                    ffma2(acc[2 * i + 1], ww, wh2.y);
                }
            }
        }
        __syncthreads();
    }

    if (t < TI) l_sh[t] = lsum[t][0] + lsum[t][1] + lsum[t][2] + lsum[t][3];

    // cross-warp reduce of acc partials via smem (reuse wh_sh: 4 warps x 32 i x 128 d)
    {
        ulonglong2* redq = (ulonglong2*)wh_sh;
#pragma unroll
        for (int i = 0; i < TI; ++i)
            redq[(wrp * TI + i) * 32 + lane] = make_ulonglong2(acc[2 * i], acc[2 * i + 1]);
    }
    __syncthreads();

    // per-row: sum partials, divide by l, LN, lrelu, maxpool
    for (int i = 0; i < TI; ++i) {
        float v = wh_sh[(0 * TI + i) * Dd + t] + wh_sh[(1 * TI + i) * Dd + t]
                + wh_sh[(2 * TI + i) * Dd + t] + wh_sh[(3 * TI + i) * Dd + t];
        v *= 1.f / l_sh[i];
        float s1 = warpSum(v);
        float s2 = warpSum(v * v);
        if (lane == 0) { rs1[wrp] = s1; rs2[wrp] = s2; }
        __syncthreads();
        float S1 = rs1[0] + rs1[1] + rs1[2] + rs1[3];
        float S2 = rs2[0] + rs2[1] + rs2[2] + rs2[3];
        __syncthreads();
        float mean = S1 * (1.f / Dd);
        float var  = S2 * (1.f / Dd) - mean * mean;
        float nv = lrelu((v - mean) * rsqrtf(var + 1e-5f));
        atomicMaxFloat(&g_pooled[(b << 7) + t], nv);
    }
}

// ---------------- K3: head + log_softmax ----------------
__global__ void k3_out(const float* __restrict__ W2, const float* __restrict__ b2,
                       float* __restrict__ out)
{
    const int t = threadIdx.x;          // 256
    const int b = t >> 5, lane = t & 31;
    if (b < Bb) {
        float p0 = 0.f, p1 = 0.f;
        for (int d = lane; d < Dd; d += 32) {
            float pv = g_pooled[b * Dd + d];
            p0 += pv * W2[d];
            p1 += pv * W2[Dd + d];
        }
        p0 = warpSum(p0);
        p1 = warpSum(p1);
        if (lane == 0) {
            float o0 = p0 + b2[0], o1 = p1 + b2[1];
            float m = fmaxf(o0, o1);
            float lse = m + logf(expf(o0 - m) + expf(o1 - m));
            out[b * 2 + 0] = o0 - lse;
            out[b * 2 + 1] = o1 - lse;
        }
    }
}

// ---------------- launch ----------------
extern "C" void kernel_launch(void* const* d_in, const int* in_sizes, int n_in,
                              void* d_out, int out_size)
{
    const float* h   = (const float*)d_in[0];
    const int*   adj = (const int*)  d_in[1];
    const float* W1  = (const float*)d_in[2];
    const float* b1  = (const float*)d_in[3];
    const float* Wg  = (const float*)d_in[4];
    const float* bg  = (const float*)d_in[5];
    const float* a1  = (const float*)d_in[6];
    const float* a2  = (const float*)d_in[7];
    const float* W2  = (const float*)d_in[8];
    const float* b2  = (const float*)d_in[9];
    float* out = (float*)d_out;

    const int smem_k1b = (128 * 132 + 128 * 128) * 4;          // 133120
    const int smem_k2  = CJ * Dd * 4 + TI * CJ * 4;            // 81920
    cudaFuncSetAttribute(k1b, cudaFuncAttributeMaxDynamicSharedMemorySize, smem_k1b);
    cudaFuncSetAttribute(k2_attn, cudaFuncAttributeMaxDynamicSharedMemorySize, smem_k2);

    k_init<<<1, Bb * Dd>>>();
    k1a<<<Bb * Nn, 128>>>(h, W1, b1);
    k1b<<<Bb * Nn / 128, 512, smem_k1b>>>(Wg, bg, a1, a2);
    k_e2max<<<Bb, 128>>>();
    k2_attn<<<Bb * (Nn / TI), 128, smem_k2>>>(adj);
    k3_out<<<1, 256>>>(W2, b2, out);
}